// round 10
// baseline (speedup 1.0000x reference)
#include <cuda_runtime.h>
#include <cuda_bf16.h>

#define EPSV 1e-8f
#define TPB 256
#define WARPS 8
#define EPT 2                    // elements per thread
#define WELEMS (32 * EPT)        // 64 elements per warp tile

__global__ void __launch_bounds__(TPB)
cov3d_kernel(const float4* __restrict__ quat,   // N x 4
             const float*  __restrict__ scale,  // N x 3
             float* __restrict__ out,           // N x 9
             int n)
{
    // Per-warp region: 64 elems * 9 floats = 576 floats (2304 B). 18 KB total.
    // Reused: first 192 floats hold staged scale, then overwritten by outputs.
    __shared__ __align__(16) float s_buf[WARPS][WELEMS * 9];

    const int warp = threadIdx.x >> 5;
    const int lane = threadIdx.x & 31;

    const int base = (blockIdx.x * WARPS + warp) * WELEMS;  // warp's first elem
    if (base < n) {                                          // warp-uniform
        const int wrem = min(WELEMS, n - base);
        float* buf = s_buf[warp];

        // ---- batch quaternion loads (2 independent LDG.128) ----
        float4 q[EPT];
        #pragma unroll
        for (int e = 0; e < EPT; e++) {
            int li = e * 32 + lane;
            if (li < wrem) q[e] = __ldcs(quat + base + li);
        }

        // ---- stage scale coalesced into smem (48 float4 per warp) ----
        if (wrem == WELEMS) {
            const float4* sp4 = (const float4*)(scale + (size_t)base * 3);
            float4* b4 = (float4*)buf;
            b4[lane] = __ldcs(sp4 + lane);
            if (lane < 16) b4[32 + lane] = __ldcs(sp4 + 32 + lane);
        } else {
            const float* sp = scale + (size_t)base * 3;
            for (int j = lane; j < wrem * 3; j += 32)
                buf[j] = __ldcs(sp + j);
        }
        __syncwarp();

        // ---- per-element scales (stride-3 smem: conflict-free) ----
        float sc[EPT][3];
        #pragma unroll
        for (int e = 0; e < EPT; e++) {
            int li = e * 32 + lane;
            if (li < wrem) {
                sc[e][0] = buf[li * 3 + 0];
                sc[e][1] = buf[li * 3 + 1];
                sc[e][2] = buf[li * 3 + 2];
            }
        }
        __syncwarp();   // scale reads done before buf is reused for outputs

        // ---- compute + stage outputs (stride-9 smem: conflict-free) ----
        #pragma unroll
        for (int e = 0; e < EPT; e++) {
            int li = e * 32 + lane;
            if (li >= wrem) continue;

            float w = q[e].x, x = q[e].y, y = q[e].z, z = q[e].w;

            float s0 = fabsf(sc[e][0]) + EPSV;
            float s1 = fabsf(sc[e][1]) + EPSV;
            float s2 = fabsf(sc[e][2]) + EPSV;
            float s0sq = s0 * s0, s1sq = s1 * s1, s2sq = s2 * s2;

            // Rotation with 1/||q||^2 folded in (R entries quadratic in q).
            float ww = w * w, xx = x * x, yy = y * y, zz = z * z;
            float inv = 1.0f / (ww + xx + yy + zz);
            float xy = x * y, xz = x * z, yz = y * z;
            float wx = w * x, wy = w * y, wz = w * z;

            float r00 = (ww + xx - yy - zz) * inv;
            float r01 = 2.0f * (xy - wz) * inv;
            float r02 = 2.0f * (xz + wy) * inv;
            float r10 = 2.0f * (xy + wz) * inv;
            float r11 = (ww - xx + yy - zz) * inv;
            float r12 = 2.0f * (yz - wx) * inv;
            float r20 = 2.0f * (xz - wy) * inv;
            float r21 = 2.0f * (yz + wx) * inv;
            float r22 = (ww - xx - yy + zz) * inv;

            // M = R diag(s^2) R^T (symmetric)
            float m00 = s0sq*r00*r00 + s1sq*r01*r01 + s2sq*r02*r02;
            float m01 = s0sq*r00*r10 + s1sq*r01*r11 + s2sq*r02*r12;
            float m02 = s0sq*r00*r20 + s1sq*r01*r21 + s2sq*r02*r22;
            float m11 = s0sq*r10*r10 + s1sq*r11*r11 + s2sq*r12*r12;
            float m12 = s0sq*r10*r20 + s1sq*r11*r21 + s2sq*r12*r22;
            float m22 = s0sq*r20*r20 + s1sq*r21*r21 + s2sq*r22*r22;

            float* o = buf + li * 9;
            o[0] = m00; o[1] = m01; o[2] = m02;
            o[3] = m01; o[4] = m11; o[5] = m12;
            o[6] = m02; o[7] = m12; o[8] = m22;
        }
        __syncwarp();

        // ---- flush: coalesced float4 streaming stores (144 float4/warp) ----
        if (wrem == WELEMS) {
            float4* o4 = (float4*)(out + (size_t)base * 9);
            const float4* b4 = (const float4*)buf;
            #pragma unroll
            for (int k = 0; k < 4; k++)
                __stcs(o4 + lane + k * 32, b4[lane + k * 32]);
            if (lane < 16)
                __stcs(o4 + 128 + lane, b4[128 + lane]);
        } else {
            float* og = out + (size_t)base * 9;
            for (int j = lane; j < wrem * 9; j += 32)
                __stcs(og + j, buf[j]);
        }
    }
}

extern "C" void kernel_launch(void* const* d_in, const int* in_sizes, int n_in,
                              void* d_out, int out_size)
{
    const float4* quat  = (const float4*)d_in[0];  // N x 4 float32
    const float*  scale = (const float*) d_in[1];  // N x 3 float32
    float* out = (float*)d_out;                    // N x 3 x 3 float32

    int n = in_sizes[0] / 4;
    int elems_per_block = TPB * EPT;               // 512
    int blocks = (n + elems_per_block - 1) / elems_per_block;
    cov3d_kernel<<<blocks, TPB>>>(quat, scale, out, n);
}

// round 11
// speedup vs baseline: 1.0089x; 1.0089x over previous
#include <cuda_runtime.h>
#include <cuda_bf16.h>

#define EPSV 1e-8f
#define TPB 128
#define WARPS 4
#define EPT 6                    // elements per thread
#define WELEMS (32 * EPT)        // 192 elements per warp tile

__global__ void __launch_bounds__(TPB)
cov3d_kernel(const float4* __restrict__ quat,   // N x 4
             const float*  __restrict__ scale,  // N x 3
             float* __restrict__ out,           // N x 9
             int n)
{
    // Per-warp region: 192 elems * 9 floats = 1728 floats (6912 B). 27 KB/blk.
    // Reused: first 576 floats hold staged scale, then overwritten by outputs.
    __shared__ __align__(16) float s_buf[WARPS][WELEMS * 9];

    const int warp = threadIdx.x >> 5;
    const int lane = threadIdx.x & 31;

    const int base = (blockIdx.x * WARPS + warp) * WELEMS;  // warp's first elem
    if (base < n) {                                          // warp-uniform
        const int wrem = min(WELEMS, n - base);
        float* buf = s_buf[warp];

        // ---- batch quaternion loads (6 independent LDG.128 in flight) ----
        float4 q[EPT];
        #pragma unroll
        for (int e = 0; e < EPT; e++) {
            int li = e * 32 + lane;
            if (li < wrem) q[e] = __ldcs(quat + base + li);
        }

        // ---- stage scale coalesced into smem (144 float4/warp: 5 more LDG) ----
        if (wrem == WELEMS) {
            const float4* sp4 = (const float4*)(scale + (size_t)base * 3);
            float4* b4 = (float4*)buf;
            #pragma unroll
            for (int k = 0; k < 4; k++)
                b4[lane + k * 32] = __ldcs(sp4 + lane + k * 32);
            if (lane < 16)
                b4[128 + lane] = __ldcs(sp4 + 128 + lane);
        } else {
            const float* sp = scale + (size_t)base * 3;
            for (int j = lane; j < wrem * 3; j += 32)
                buf[j] = __ldcs(sp + j);
        }
        __syncwarp();

        // ---- per-element scales (stride-3 smem: conflict-free) ----
        float sc[EPT][3];
        #pragma unroll
        for (int e = 0; e < EPT; e++) {
            int li = e * 32 + lane;
            if (li < wrem) {
                sc[e][0] = buf[li * 3 + 0];
                sc[e][1] = buf[li * 3 + 1];
                sc[e][2] = buf[li * 3 + 2];
            }
        }
        __syncwarp();   // scale reads done before buf is reused for outputs

        // ---- compute + stage outputs (stride-9 smem: conflict-free) ----
        #pragma unroll
        for (int e = 0; e < EPT; e++) {
            int li = e * 32 + lane;
            if (li >= wrem) continue;

            float w = q[e].x, x = q[e].y, y = q[e].z, z = q[e].w;

            float s0 = fabsf(sc[e][0]) + EPSV;
            float s1 = fabsf(sc[e][1]) + EPSV;
            float s2 = fabsf(sc[e][2]) + EPSV;
            float s0sq = s0 * s0, s1sq = s1 * s1, s2sq = s2 * s2;

            // Rotation with 1/||q||^2 folded in (R entries quadratic in q).
            float ww = w * w, xx = x * x, yy = y * y, zz = z * z;
            float inv = 1.0f / (ww + xx + yy + zz);
            float xy = x * y, xz = x * z, yz = y * z;
            float wx = w * x, wy = w * y, wz = w * z;

            float r00 = (ww + xx - yy - zz) * inv;
            float r01 = 2.0f * (xy - wz) * inv;
            float r02 = 2.0f * (xz + wy) * inv;
            float r10 = 2.0f * (xy + wz) * inv;
            float r11 = (ww - xx + yy - zz) * inv;
            float r12 = 2.0f * (yz - wx) * inv;
            float r20 = 2.0f * (xz - wy) * inv;
            float r21 = 2.0f * (yz + wx) * inv;
            float r22 = (ww - xx - yy + zz) * inv;

            // M = R diag(s^2) R^T (symmetric)
            float m00 = s0sq*r00*r00 + s1sq*r01*r01 + s2sq*r02*r02;
            float m01 = s0sq*r00*r10 + s1sq*r01*r11 + s2sq*r02*r12;
            float m02 = s0sq*r00*r20 + s1sq*r01*r21 + s2sq*r02*r22;
            float m11 = s0sq*r10*r10 + s1sq*r11*r11 + s2sq*r12*r12;
            float m12 = s0sq*r10*r20 + s1sq*r11*r21 + s2sq*r12*r22;
            float m22 = s0sq*r20*r20 + s1sq*r21*r21 + s2sq*r22*r22;

            float* o = buf + li * 9;
            o[0] = m00; o[1] = m01; o[2] = m02;
            o[3] = m01; o[4] = m11; o[5] = m12;
            o[6] = m02; o[7] = m12; o[8] = m22;
        }
        __syncwarp();

        // ---- flush: coalesced float4 streaming stores (432 float4/warp) ----
        if (wrem == WELEMS) {
            float4* o4 = (float4*)(out + (size_t)base * 9);
            const float4* b4 = (const float4*)buf;
            #pragma unroll
            for (int k = 0; k < 13; k++)
                __stcs(o4 + lane + k * 32, b4[lane + k * 32]);
            if (lane < 16)
                __stcs(o4 + 416 + lane, b4[416 + lane]);
        } else {
            float* og = out + (size_t)base * 9;
            for (int j = lane; j < wrem * 9; j += 32)
                __stcs(og + j, buf[j]);
        }
    }
}

extern "C" void kernel_launch(void* const* d_in, const int* in_sizes, int n_in,
                              void* d_out, int out_size)
{
    const float4* quat  = (const float4*)d_in[0];  // N x 4 float32
    const float*  scale = (const float*) d_in[1];  // N x 3 float32
    float* out = (float*)d_out;                    // N x 3 x 3 float32

    int n = in_sizes[0] / 4;
    int elems_per_block = TPB * EPT;               // 768
    int blocks = (n + elems_per_block - 1) / elems_per_block;
    cov3d_kernel<<<blocks, TPB>>>(quat, scale, out, n);
}